// round 15
// baseline (speedup 1.0000x reference)
#include <cuda_runtime.h>
#include <cuda_bf16.h>
#include <mma.h>
#include <math_constants.h>
#include <cstdint>

using namespace nvcuda;
typedef __nv_bfloat16 bf16;

#define BB 4
#define CC 256
#define AA 4096

#if defined(__CUDA_ARCH_FEAT_SM103_ALL) || defined(__CUDA_ARCH_FEAT_SM100_ALL) || \
    defined(__CUDA_ARCH_FEAT_SM101_ALL) || defined(__CUDA_ARCH_FEAT_SM110_ALL)
#define HAS_TC 1
#else
#define HAS_TC 0
#endif

// ---- device scratch ----
__device__ __align__(1024) bf16  g_Eh [(long)BB * AA * AA];    // exp(S-60) hi
__device__ __align__(1024) bf16  g_El [(long)BB * AA * AA];
__device__ __align__(1024) bf16  g_ETh[(long)BB * AA * AA];    // transposed
__device__ __align__(1024) bf16  g_ETl[(long)BB * AA * AA];
__device__ __align__(1024) bf16  g_VaH[(long)BB * CC * AA], g_VaL[(long)BB * CC * AA];
__device__ __align__(1024) bf16  g_VbH[(long)BB * CC * AA], g_VbL[(long)BB * CC * AA];
__device__ __align__(1024) bf16  g_VaTh[(long)BB * AA * CC], g_VaTl[(long)BB * AA * CC];
__device__ __align__(1024) bf16  g_VbTh[(long)BB * AA * CC], g_VbTl[(long)BB * AA * CC];
__device__ __align__(1024) bf16  g_VbWTh[(long)BB * AA * CC], g_VbWTl[(long)BB * AA * CC];
__device__ __align__(1024) bf16  g_WTh[CC * CC], g_WTl[CC * CC];
__device__ float g_rp[(long)BB * 16 * AA], g_cp[(long)BB * 32 * AA];
__device__ float g_irs[BB * AA], g_ics[BB * AA];

// ============================================================
// helpers
// ============================================================
__device__ __forceinline__ uint32_t smem_u32(const void* p) {
    uint32_t a;
    asm("{ .reg .u64 t; cvta.to.shared.u64 t, %1; cvt.u32.u64 %0, t; }" : "=r"(a) : "l"(p));
    return a;
}
__device__ __forceinline__ uint32_t cvt2(float lo, float hi) {
    uint32_t r;
    asm("cvt.rn.bf16x2.f32 %0, %1, %2;" : "=r"(r) : "f"(hi), "f"(lo));
    return r;
}
__device__ __forceinline__ void split8(const float* v, uint4& H, uint4& L) {
    uint32_t h[4], l[4];
#pragma unroll
    for (int i = 0; i < 4; i++) {
        float a = v[2 * i], b = v[2 * i + 1];
        h[i] = cvt2(a, b);
        float ar = a - __uint_as_float(h[i] << 16);
        float br = b - __uint_as_float(h[i] & 0xFFFF0000u);
        l[i] = cvt2(ar, br);
    }
    H = make_uint4(h[0], h[1], h[2], h[3]);
    L = make_uint4(l[0], l[1], l[2], l[3]);
}
__device__ __forceinline__ int sw128(int off) { return off ^ ((off >> 3) & 0x70); }

#if HAS_TC
__device__ __forceinline__ uint32_t elect_one() {
    uint32_t p;
    asm volatile("{ .reg .pred p; elect.sync _|p, 0xFFFFFFFF; selp.b32 %0, 1, 0, p; }" : "=r"(p));
    return p;
}
__device__ __forceinline__ void mbar_init(uint32_t m, uint32_t cnt) {
    asm volatile("mbarrier.init.shared.b64 [%0], %1;" :: "r"(m), "r"(cnt) : "memory");
}
__device__ __forceinline__ void mbar_wait(uint32_t m, uint32_t par) {
    asm volatile(
        "{\n\t.reg .pred P;\n\t"
        "W_%=:\n\t"
        "mbarrier.try_wait.parity.acquire.cta.shared::cta.b64 P, [%0], %1, 0x989680;\n\t"
        "@P bra.uni D_%=;\n\t"
        "bra.uni W_%=;\n\t"
        "D_%=:\n\t}"
        :: "r"(m), "r"(par) : "memory");
}
__device__ __forceinline__ void tmem_alloc(uint32_t dst, uint32_t ncols) {
    asm volatile("tcgen05.alloc.cta_group::1.sync.aligned.shared::cta.b32 [%0], %1;"
                 :: "r"(dst), "r"(ncols) : "memory");
}
__device__ __forceinline__ void tmem_dealloc(uint32_t t, uint32_t ncols) {
    asm volatile("tcgen05.relinquish_alloc_permit.cta_group::1.sync.aligned;");
    asm volatile("tcgen05.dealloc.cta_group::1.sync.aligned.b32 %0, %1;" :: "r"(t), "r"(ncols));
}
__device__ __forceinline__ void tc_commit(uint32_t mbar) {
    asm volatile("tcgen05.commit.cta_group::1.mbarrier::arrive::one.shared::cluster.b64 [%0];"
                 :: "r"(mbar) : "memory");
}
__device__ __forceinline__ void mma_f16_ss(uint32_t d, uint64_t ad, uint64_t bd,
                                           uint32_t idesc, bool accum) {
    uint32_t en = accum ? 1u : 0u;
    asm volatile(
        "{\n\t.reg .pred p;\n\tsetp.ne.u32 p, %4, 0;\n\t"
        "tcgen05.mma.cta_group::1.kind::f16 [%0], %1, %2, %3, {%5, %5, %5, %5}, p;\n\t}"
        :: "r"(d), "l"(ad), "l"(bd), "r"(idesc), "r"(en), "r"(0u) : "memory");
}
__device__ __forceinline__ void cp16(uint32_t dst, const void* src) {
    asm volatile("cp.async.cg.shared.global [%0], [%1], 16;" :: "r"(dst), "l"(src));
}
#define CP_COMMIT() asm volatile("cp.async.commit_group;" ::: "memory")
#define CP_WAIT1()  asm volatile("cp.async.wait_group 1;" ::: "memory")
#define CP_WAIT0()  asm volatile("cp.async.wait_group 0;" ::: "memory")
#define TC_FENCE_AFTER()  asm volatile("tcgen05.fence::after_thread_sync;" ::: "memory")
#define TC_FENCE_BEFORE() asm volatile("tcgen05.fence::before_thread_sync;" ::: "memory")
#define PROXY_FENCE()     asm volatile("fence.proxy.async.shared::cta;" ::: "memory")
#define TC_WAIT_LD()      asm volatile("tcgen05.wait::ld.sync.aligned;" ::: "memory")

#define TC_LD_X32(r, addr) \
    asm volatile("tcgen05.ld.sync.aligned.32x32b.x32.b32 " \
        "{%0,%1,%2,%3,%4,%5,%6,%7,%8,%9,%10,%11,%12,%13,%14,%15," \
        "%16,%17,%18,%19,%20,%21,%22,%23,%24,%25,%26,%27,%28,%29,%30,%31}, [%32];" \
        : "=r"((r)[0]),"=r"((r)[1]),"=r"((r)[2]),"=r"((r)[3]), \
          "=r"((r)[4]),"=r"((r)[5]),"=r"((r)[6]),"=r"((r)[7]), \
          "=r"((r)[8]),"=r"((r)[9]),"=r"((r)[10]),"=r"((r)[11]), \
          "=r"((r)[12]),"=r"((r)[13]),"=r"((r)[14]),"=r"((r)[15]), \
          "=r"((r)[16]),"=r"((r)[17]),"=r"((r)[18]),"=r"((r)[19]), \
          "=r"((r)[20]),"=r"((r)[21]),"=r"((r)[22]),"=r"((r)[23]), \
          "=r"((r)[24]),"=r"((r)[25]),"=r"((r)[26]),"=r"((r)[27]), \
          "=r"((r)[28]),"=r"((r)[29]),"=r"((r)[30]),"=r"((r)[31]) \
        : "r"(addr))
#endif

static constexpr uint64_t DESC_BASE_SW128 =
    (uint64_t(2) << 61) | (uint64_t(1) << 46) | (uint64_t(64) << 32) | (uint64_t(1) << 16);
__device__ __forceinline__ uint64_t mk_desc(uint32_t addr) {
    return DESC_BASE_SW128 | ((uint64_t)(addr >> 4) & 0x3FFF);
}

// ============================================================
// main GEMM: CTA tile 128m x 256n, K-stage 64, pure cp.async producers.
// C[m][n] = sum_k A[m][k]*B[n][k], A/B pre-split bf16 hi/lo.
// EPI 0: fp32 store to Cf (ldc)
// EPI 1: bf16 hi/lo split store to Coh/Col (ldc)
// EPI 2: exp(x-60) -> E/ET bf16 hi/lo + row/col partial sums
// ============================================================
#define OFF_MBAR 0
#define OFF_TMEM 32
#define STG_B (96 * 1024)
#define OFF_BUF(s) (1024 + (s) * STG_B)
#define SMEM_NEED (1024 + 2 * STG_B + 1024)
#define TLD 257

static constexpr uint32_t IDESC =
    (1u << 4) | (1u << 7) | (1u << 10) | ((256 / 8) << 17) | ((128 / 16) << 24);

// common EPI-2 tile epilogue: tile holds fp32 S values [128][TLD]
__device__ __forceinline__ void epi_exp(float* tile, int b, int m0, int n0,
                                        int bx, int by, int tid) {
    // phase a: exp + E store + row sums (thread t: row r=t>>1, half h=t&1)
    {
        const int r = tid >> 1, h = tid & 1;
        float* trow = tile + r * TLD + h * 128;
        float rsum = 0.f;
#pragma unroll
        for (int g = 0; g < 16; g++) {
            float e[8];
#pragma unroll
            for (int i = 0; i < 8; i++) {
                e[i] = __expf(trow[g * 8 + i] - 60.f);
                rsum += e[i];
                trow[g * 8 + i] = e[i];
            }
            uint4 H, L; split8(e, H, L);
            const long off = ((long)b * AA + m0 + r) * AA + n0 + h * 128 + g * 8;
            *(uint4*)(g_Eh + off) = H;
            *(uint4*)(g_El + off) = L;
        }
        rsum += __shfl_xor_sync(0xffffffffu, rsum, 1);
        if (h == 0) g_rp[((long)b * 16 + bx) * AA + m0 + r] = rsum;
    }
    __syncthreads();
    // phase b: ET store + col sums (thread t: column n=t)
    {
        const int n = tid;
        float csum = 0.f;
#pragma unroll
        for (int g = 0; g < 16; g++) {
            float e[8];
#pragma unroll
            for (int i = 0; i < 8; i++) {
                e[i] = tile[(g * 8 + i) * TLD + n];
                csum += e[i];
            }
            uint4 H, L; split8(e, H, L);
            const long off = ((long)b * AA + n0 + n) * AA + m0 + g * 8;
            *(uint4*)(g_ETh + off) = H;
            *(uint4*)(g_ETl + off) = L;
        }
        g_cp[((long)b * 32 + by) * AA + n0 + n] = csum;
    }
}

template<int EPI>
__global__ void __launch_bounds__(256) k_gemm(
    const bf16* __restrict__ Agh, const bf16* __restrict__ Agl, long sA, int lda,
    const bf16* __restrict__ Bgh, const bf16* __restrict__ Bgl, long sB, int ldb,
    float* __restrict__ Cf, bf16* __restrict__ Coh, bf16* __restrict__ Col,
    long sC, int ldc, int K)
{
    extern __shared__ char smraw[];
    char* sm = (char*)(((uintptr_t)smraw + 1023) & ~(uintptr_t)1023);
    float* tile = (float*)(sm + 1024);    // reuses pipeline buffers post-mainloop
    const int tid = threadIdx.x, wid = tid >> 5, lid = tid & 31;
    const int b = blockIdx.z;
    const int m0 = blockIdx.y * 128, n0 = blockIdx.x * 256;
    const bf16* Ah = Agh + (long)b * sA + (long)m0 * lda;
    const bf16* Al = Agl + (long)b * sA + (long)m0 * lda;
    const bf16* Bh = Bgh + (long)b * sB + (long)n0 * ldb;
    const bf16* Bl = Bgl + (long)b * sB + (long)n0 * ldb;

#if HAS_TC
    const uint32_t sb = smem_u32(sm);
    if (tid == 0) { mbar_init(sb + OFF_MBAR, 1); mbar_init(sb + OFF_MBAR + 8, 1); }
    if (wid == 0) tmem_alloc(sb + OFF_TMEM, 256);
    __syncthreads();
    uint32_t tmem;
    asm volatile("ld.shared.b32 %0, [%1];" : "=r"(tmem) : "r"(sb + OFF_TMEM));

    const int nst = K / 64;
    auto issue = [&](int s) {
        const uint32_t bufb = sb + OFF_BUF(s & 1);
        const int k0 = s * 64;
#pragma unroll
        for (int i = 0; i < 4; i++) {           // A: 128 rows x 8 chunks
            int idx = tid + i * 256;
            int r = idx >> 3, ch = idx & 7;
            uint32_t d = bufb + (uint32_t)sw128(r * 128 + ch * 16);
            const long so = (long)r * lda + k0 + ch * 8;
            cp16(d, Ah + so);
            cp16(d + 16 * 1024, Al + so);
        }
#pragma unroll
        for (int i = 0; i < 8; i++) {           // B: 256 rows x 8 chunks
            int idx = tid + i * 256;
            int r = idx >> 3, ch = idx & 7;
            uint32_t d = bufb + 32 * 1024 + (uint32_t)sw128(r * 128 + ch * 16);
            const long so = (long)r * ldb + k0 + ch * 8;
            cp16(d, Bh + so);
            cp16(d + 32 * 1024, Bl + so);
        }
        CP_COMMIT();
    };

    issue(0);
    issue(1);
    int ph0 = 0, ph1 = 0;
    for (int s = 0; s < nst; s++) {
        const int buf = s & 1;
        if (s + 1 < nst) CP_WAIT1(); else CP_WAIT0();
        PROXY_FENCE();
        __syncthreads();
        if (wid == 0 && elect_one()) {
            const uint32_t bufb = sb + OFF_BUF(buf);
            uint64_t adh = mk_desc(bufb);
            uint64_t adl = mk_desc(bufb + 16 * 1024);
            uint64_t bdh = mk_desc(bufb + 32 * 1024);
            uint64_t bdl = mk_desc(bufb + 64 * 1024);
#pragma unroll
            for (int k = 0; k < 4; k++) {
                mma_f16_ss(tmem, adh + k * 2, bdh + k * 2, IDESC, !(s == 0 && k == 0));
                mma_f16_ss(tmem, adh + k * 2, bdl + k * 2, IDESC, true);
                mma_f16_ss(tmem, adl + k * 2, bdh + k * 2, IDESC, true);
            }
            tc_commit(sb + OFF_MBAR + buf * 8);
        }
        if (s + 2 < nst) {
            if (buf == 0) { mbar_wait(sb + OFF_MBAR, ph0); ph0 ^= 1; }
            else          { mbar_wait(sb + OFF_MBAR + 8, ph1); ph1 ^= 1; }
            issue(s + 2);
        }
    }
    mbar_wait(sb + OFF_MBAR, ph0);
    mbar_wait(sb + OFF_MBAR + 8, ph1);
    TC_FENCE_AFTER();

    // ---- epilogue: 8 warps, warp w: rows=(w&3)*32+lid, col half=(w>>2)*128 ----
    {
        const int row = (wid & 3) * 32 + lid;
        const int half = wid >> 2;
#pragma unroll
        for (int ch = 0; ch < 4; ch++) {
            uint32_t r[32];
            TC_LD_X32(r, tmem + half * 128 + ch * 32);
            TC_WAIT_LD();
            if (EPI == 0) {
                float* dst = Cf + (long)b * sC + (long)(m0 + row) * ldc
                             + n0 + half * 128 + ch * 32;
#pragma unroll
                for (int j = 0; j < 32; j += 4) {
                    float4 o = make_float4(__uint_as_float(r[j]),   __uint_as_float(r[j+1]),
                                           __uint_as_float(r[j+2]), __uint_as_float(r[j+3]));
                    *(float4*)(dst + j) = o;
                }
            } else if (EPI == 1) {
                const long off = (long)b * sC + (long)(m0 + row) * ldc
                                 + n0 + half * 128 + ch * 32;
#pragma unroll
                for (int g = 0; g < 4; g++) {
                    float e[8];
#pragma unroll
                    for (int i = 0; i < 8; i++) e[i] = __uint_as_float(r[g * 8 + i]);
                    uint4 H, L; split8(e, H, L);
                    *(uint4*)(Coh + off + g * 8) = H;
                    *(uint4*)(Col + off + g * 8) = L;
                }
            } else {
                float* trow = tile + row * TLD + half * 128 + ch * 32;
#pragma unroll
                for (int j = 0; j < 32; j++) trow[j] = __uint_as_float(r[j]);
            }
        }
        TC_FENCE_BEFORE();
    }
    __syncthreads();
    if (wid == 0) tmem_dealloc(tmem, 256);
    if (EPI == 2) {
        __syncthreads();
        epi_exp(tile, b, m0, n0, blockIdx.x, blockIdx.y, tid);
    }

#else  // ---------- wmma fallback (insurance only) ----------
    float* scratch = tile + 128 * TLD;   // 8 warps x 256 floats
    const int wm = wid >> 1, wn = wid & 1;
    for (int nc = 0; nc < 2; nc++) {
        wmma::fragment<wmma::accumulator, 16, 16, 16, float> acc[2][4];
#pragma unroll
        for (int i = 0; i < 2; i++)
#pragma unroll
            for (int j = 0; j < 4; j++) wmma::fill_fragment(acc[i][j], 0.f);
        for (int k0 = 0; k0 < K; k0 += 16) {
            wmma::fragment<wmma::matrix_a, 16, 16, 16, bf16, wmma::row_major> ah, al;
            wmma::fragment<wmma::matrix_b, 16, 16, 16, bf16, wmma::col_major> bh, bl;
#pragma unroll
            for (int i = 0; i < 2; i++) {
                long offA = (long)(wm * 32 + i * 16) * lda + k0;
                wmma::load_matrix_sync(ah, Ah + offA, lda);
                wmma::load_matrix_sync(al, Al + offA, lda);
#pragma unroll
                for (int j = 0; j < 4; j++) {
                    long offB = (long)(nc * 128 + wn * 64 + j * 16) * ldb + k0;
                    wmma::load_matrix_sync(bh, Bh + offB, ldb);
                    wmma::load_matrix_sync(bl, Bl + offB, ldb);
                    wmma::mma_sync(acc[i][j], ah, bh, acc[i][j]);
                    wmma::mma_sync(acc[i][j], ah, bl, acc[i][j]);
                    wmma::mma_sync(acc[i][j], al, bh, acc[i][j]);
                }
            }
        }
        if (EPI == 0) {
#pragma unroll
            for (int i = 0; i < 2; i++)
#pragma unroll
                for (int j = 0; j < 4; j++)
                    wmma::store_matrix_sync(Cf + (long)b * sC
                                            + (long)(m0 + wm * 32 + i * 16) * ldc
                                            + n0 + nc * 128 + wn * 64 + j * 16,
                                            acc[i][j], ldc, wmma::mem_row_major);
        } else {
            // stage via per-warp scratch into tile
#pragma unroll
            for (int i = 0; i < 2; i++)
#pragma unroll
                for (int j = 0; j < 4; j++) {
                    wmma::store_matrix_sync(scratch + wid * 256, acc[i][j], 16,
                                            wmma::mem_row_major);
                    __syncwarp();
#pragma unroll
                    for (int e = 0; e < 8; e++) {
                        int idx = lid + e * 32;
                        int rr = idx >> 4, cc = idx & 15;
                        tile[(wm * 32 + i * 16 + rr) * TLD
                             + nc * 128 + wn * 64 + j * 16 + cc] =
                            scratch[wid * 256 + rr * 16 + cc];
                    }
                    __syncwarp();
                }
        }
    }
    if (EPI == 1) {
        __syncthreads();
        const int r = tid >> 1, h = tid & 1;
        const long off0 = (long)b * sC + (long)(m0 + r) * ldc + n0 + h * 128;
#pragma unroll
        for (int g = 0; g < 16; g++) {
            float e[8];
#pragma unroll
            for (int i = 0; i < 8; i++) e[i] = tile[r * TLD + h * 128 + g * 8 + i];
            uint4 H, L; split8(e, H, L);
            *(uint4*)(Coh + off0 + g * 8) = H;
            *(uint4*)(Col + off0 + g * 8) = L;
        }
    } else if (EPI == 2) {
        __syncthreads();
        epi_exp(tile, b, m0, n0, blockIdx.x, blockIdx.y, tid);
    }
#endif
}

// ---- combine partial sums -> inverse sums ----
__global__ void __launch_bounds__(256) k_combine() {
    const int idx = blockIdx.x * 256 + threadIdx.x;
    const int b = idx / AA, x = idx % AA;
    float rs = 0.f, cs = 0.f;
#pragma unroll
    for (int j = 0; j < 16; j++) rs += g_rp[((long)b * 16 + j) * AA + x];
#pragma unroll
    for (int j = 0; j < 32; j++) cs += g_cp[((long)b * 32 + j) * AA + x];
    g_irs[idx] = 1.f / rs;
    g_ics[idx] = 1.f / cs;
}

// ---- elementwise fp32 -> bf16 hi/lo split ----
__global__ void __launch_bounds__(256) k_split(const float* __restrict__ in,
                                               bf16* __restrict__ oh,
                                               bf16* __restrict__ ol) {
    const long i8 = (long)blockIdx.x * 256 + threadIdx.x;
    float v[8];
    *(float4*)(v)     = __ldg((const float4*)in + i8 * 2);
    *(float4*)(v + 4) = __ldg((const float4*)in + i8 * 2 + 1);
    uint4 H, L; split8(v, H, L);
    *(uint4*)(oh + i8 * 8) = H;
    *(uint4*)(ol + i8 * 8) = L;
}

// ---- generic transpose + split: src[b][r][c] ([R][Cc]) -> out[b][c][r] ----
__global__ void __launch_bounds__(256) k_tsplit(const float* __restrict__ src,
                                                bf16* __restrict__ oh,
                                                bf16* __restrict__ ol,
                                                int R, int Cc, long sbatch) {
    __shared__ float t[32][33];
    const long b = blockIdx.z;
    const int c0 = blockIdx.x * 32, r0 = blockIdx.y * 32;
    const float* s = src + b * sbatch;
    bf16* doh = oh + b * sbatch;
    bf16* dol = ol + b * sbatch;
    const int x = threadIdx.x & 31, y = threadIdx.x >> 5;
#pragma unroll
    for (int i = 0; i < 32; i += 8)
        t[y + i][x] = s[(long)(r0 + y + i) * Cc + c0 + x];
    __syncthreads();
#pragma unroll
    for (int p = 0; p < 2; p++) {
        int idx = threadIdx.x + p * 256;
        int orow = idx >> 4, cp = idx & 15;
        float v0 = t[cp * 2][orow], v1 = t[cp * 2 + 1][orow];
        uint32_t hp = cvt2(v0, v1);
        float q0 = v0 - __uint_as_float(hp << 16);
        float q1 = v1 - __uint_as_float(hp & 0xFFFF0000u);
        uint32_t lp = cvt2(q0, q1);
        long o = (long)(c0 + orow) * R + r0 + cp * 2;
        *(uint32_t*)(doh + o) = hp;
        *(uint32_t*)(dol + o) = lp;
    }
}

// ---- gate + normalize + in-place scale + concat-copy ----
__global__ void __launch_bounds__(256) k_gate(const float* __restrict__ Wg,
                                              const float* __restrict__ Va,
                                              const float* __restrict__ Vb,
                                              float* __restrict__ out) {
    const int side = blockIdx.z, b = blockIdx.y;
    const int n = blockIdx.x * 256 + threadIdx.x;
    const float* orig = (side ? Vb : Va) + (long)b * CC * AA + n;
    const float isn = (side ? g_irs : g_ics)[b * AA + n];
    float* att = out + ((long)(side * BB + b)) * (2L * CC * AA) + n;
    float dot = 0.f;
#pragma unroll 4
    for (int c = 0; c < CC; c++) dot = fmaf(att[(long)c * AA] * isn, Wg[c], dot);
    float mask = isn / (1.f + __expf(-dot));
#pragma unroll 4
    for (int c = 0; c < CC; c++) {
        att[(long)c * AA] *= mask;
        att[(long)(c + CC) * AA] = orig[(long)c * AA];
    }
}

__global__ void k_tail(float* __restrict__ out, long start, long total,
                       const int* __restrict__ isz) {
    long i = start + blockIdx.x * 256L + threadIdx.x;
    if (i < total) out[i] = (float)(*isz);
}

extern "C" void kernel_launch(void* const* d_in, const int* in_sizes, int n_in,
                              void* d_out, int out_size) {
    const float* Va = (const float*)d_in[0];
    const float* Vb = (const float*)d_in[1];
    const float* Wl = (const float*)d_in[2];
    const float* Wg = (const float*)d_in[3];
    const int* isz = (const int*)d_in[4];
    float* out = (float*)d_out;

    bf16 *VaH, *VaL, *VbH, *VbL, *VaTh, *VaTl, *VbTh, *VbTl;
    bf16 *VbWTh, *VbWTl, *WTh, *WTl, *Eh, *El, *ETh, *ETl;
    cudaGetSymbolAddress((void**)&VaH, g_VaH);   cudaGetSymbolAddress((void**)&VaL, g_VaL);
    cudaGetSymbolAddress((void**)&VbH, g_VbH);   cudaGetSymbolAddress((void**)&VbL, g_VbL);
    cudaGetSymbolAddress((void**)&VaTh, g_VaTh); cudaGetSymbolAddress((void**)&VaTl, g_VaTl);
    cudaGetSymbolAddress((void**)&VbTh, g_VbTh); cudaGetSymbolAddress((void**)&VbTl, g_VbTl);
    cudaGetSymbolAddress((void**)&VbWTh, g_VbWTh); cudaGetSymbolAddress((void**)&VbWTl, g_VbWTl);
    cudaGetSymbolAddress((void**)&WTh, g_WTh);   cudaGetSymbolAddress((void**)&WTl, g_WTl);
    cudaGetSymbolAddress((void**)&Eh, g_Eh);     cudaGetSymbolAddress((void**)&El, g_El);
    cudaGetSymbolAddress((void**)&ETh, g_ETh);   cudaGetSymbolAddress((void**)&ETl, g_ETl);

    cudaFuncSetAttribute(k_gemm<0>, cudaFuncAttributeMaxDynamicSharedMemorySize, SMEM_NEED);
    cudaFuncSetAttribute(k_gemm<1>, cudaFuncAttributeMaxDynamicSharedMemorySize, SMEM_NEED);
    cudaFuncSetAttribute(k_gemm<2>, cudaFuncAttributeMaxDynamicSharedMemorySize, SMEM_NEED);

    const long NCA = (long)BB * CC * AA;

    // 1) pre-split + transposes
    k_split<<<(unsigned)(NCA / 2048), 256>>>(Va, VaH, VaL);
    k_split<<<(unsigned)(NCA / 2048), 256>>>(Vb, VbH, VbL);
    k_tsplit<<<dim3(AA / 32, CC / 32, BB), 256>>>(Va, VaTh, VaTl, CC, AA, (long)CC * AA);
    k_tsplit<<<dim3(AA / 32, CC / 32, BB), 256>>>(Vb, VbTh, VbTl, CC, AA, (long)CC * AA);
    k_tsplit<<<dim3(CC / 32, CC / 32, 1), 256>>>(Wl, WTh, WTl, CC, CC, 0);
    // 2) VbWT[n][c] = sum_d VbT[n][d] * WT[c][d]   (tcgen05, split-out)
    k_gemm<1><<<dim3(1, AA / 128, BB), 256, SMEM_NEED>>>(
        VbTh, VbTl, (long)AA * CC, CC,
        WTh, WTl, 0, CC,
        nullptr, VbWTh, VbWTl, (long)AA * CC, CC, CC);
    // 3) S GEMM fused: S[a][n] = sum_c VaT[a][c]*VbWT[n][c]; epilogue -> E/ET + sums
    k_gemm<2><<<dim3(AA / 256, AA / 128, BB), 256, SMEM_NEED>>>(
        VaTh, VaTl, (long)AA * CC, CC,
        VbWTh, VbWTl, (long)AA * CC, CC,
        nullptr, nullptr, nullptr, 0, 0, CC);
    k_combine<<<BB * AA / 256, 256>>>();
    // 4) Va_att_unscaled[c][n] = sum_a Vb[c][a] * ET[n][a]   -> out[0:B]
    k_gemm<0><<<dim3(AA / 256, CC / 128, BB), 256, SMEM_NEED>>>(
        VbH, VbL, (long)CC * AA, AA,
        ETh, ETl, (long)AA * AA, AA,
        out, nullptr, nullptr, 2L * CC * AA, AA, AA);
    // 5) Vb_att_unscaled[c][n] = sum_a Va[c][a] * E[n][a]    -> out[B:2B]
    k_gemm<0><<<dim3(AA / 256, CC / 128, BB), 256, SMEM_NEED>>>(
        VaH, VaL, (long)CC * AA, AA,
        Eh, El, (long)AA * AA, AA,
        out + (long)BB * 2 * CC * AA, nullptr, nullptr, 2L * CC * AA, AA, AA);
    // 6) gate: normalize + mask + concat
    k_gate<<<dim3(AA / 256, BB, 2), 256>>>(Wg, Va, Vb, out);
    // 7) optional tail
    long main_elems = 2L * BB * 2 * CC * AA;
    if ((long)out_size > main_elems) {
        long rem = (long)out_size - main_elems;
        k_tail<<<(unsigned)((rem + 255) / 256), 256>>>(out, main_elems, out_size, isz);
    }
}

// round 16
// speedup vs baseline: 1.0117x; 1.0117x over previous
#include <cuda_runtime.h>
#include <cuda_bf16.h>
#include <mma.h>
#include <math_constants.h>
#include <cstdint>

using namespace nvcuda;
typedef __nv_bfloat16 bf16;

#define BB 4
#define CC 256
#define AA 4096

#if defined(__CUDA_ARCH_FEAT_SM103_ALL) || defined(__CUDA_ARCH_FEAT_SM100_ALL) || \
    defined(__CUDA_ARCH_FEAT_SM101_ALL) || defined(__CUDA_ARCH_FEAT_SM110_ALL)
#define HAS_TC 1
#else
#define HAS_TC 0
#endif

// ---- device scratch ----
__device__ __align__(1024) bf16  g_Eh [(long)BB * AA * AA];    // exp(S-60) hi
__device__ __align__(1024) bf16  g_El [(long)BB * AA * AA];
__device__ __align__(1024) bf16  g_ETh[(long)BB * AA * AA];    // transposed
__device__ __align__(1024) bf16  g_ETl[(long)BB * AA * AA];
__device__ __align__(1024) bf16  g_VaH[(long)BB * CC * AA], g_VaL[(long)BB * CC * AA];
__device__ __align__(1024) bf16  g_VbH[(long)BB * CC * AA], g_VbL[(long)BB * CC * AA];
__device__ __align__(1024) bf16  g_VaTh[(long)BB * AA * CC], g_VaTl[(long)BB * AA * CC];
__device__ __align__(1024) bf16  g_VbTh[(long)BB * AA * CC], g_VbTl[(long)BB * AA * CC];
__device__ __align__(1024) bf16  g_VbWTh[(long)BB * AA * CC], g_VbWTl[(long)BB * AA * CC];
__device__ __align__(1024) bf16  g_WTh[CC * CC], g_WTl[CC * CC];
__device__ float g_rp[(long)BB * 16 * AA], g_cp[(long)BB * 32 * AA];
__device__ float g_irs[BB * AA], g_ics[BB * AA];

// ============================================================
// helpers
// ============================================================
__device__ __forceinline__ uint32_t smem_u32(const void* p) {
    uint32_t a;
    asm("{ .reg .u64 t; cvta.to.shared.u64 t, %1; cvt.u32.u64 %0, t; }" : "=r"(a) : "l"(p));
    return a;
}
__device__ __forceinline__ uint32_t cvt2(float lo, float hi) {
    uint32_t r;
    asm("cvt.rn.bf16x2.f32 %0, %1, %2;" : "=r"(r) : "f"(hi), "f"(lo));
    return r;
}
__device__ __forceinline__ void split8(const float* v, uint4& H, uint4& L) {
    uint32_t h[4], l[4];
#pragma unroll
    for (int i = 0; i < 4; i++) {
        float a = v[2 * i], b = v[2 * i + 1];
        h[i] = cvt2(a, b);
        float ar = a - __uint_as_float(h[i] << 16);
        float br = b - __uint_as_float(h[i] & 0xFFFF0000u);
        l[i] = cvt2(ar, br);
    }
    H = make_uint4(h[0], h[1], h[2], h[3]);
    L = make_uint4(l[0], l[1], l[2], l[3]);
}
__device__ __forceinline__ int sw128(int off) { return off ^ ((off >> 3) & 0x70); }

#if HAS_TC
__device__ __forceinline__ uint32_t elect_one() {
    uint32_t p;
    asm volatile("{ .reg .pred p; elect.sync _|p, 0xFFFFFFFF; selp.b32 %0, 1, 0, p; }" : "=r"(p));
    return p;
}
__device__ __forceinline__ void mbar_init(uint32_t m, uint32_t cnt) {
    asm volatile("mbarrier.init.shared.b64 [%0], %1;" :: "r"(m), "r"(cnt) : "memory");
}
__device__ __forceinline__ void mbar_wait(uint32_t m, uint32_t par) {
    asm volatile(
        "{\n\t.reg .pred P;\n\t"
        "W_%=:\n\t"
        "mbarrier.try_wait.parity.acquire.cta.shared::cta.b64 P, [%0], %1, 0x989680;\n\t"
        "@P bra.uni D_%=;\n\t"
        "bra.uni W_%=;\n\t"
        "D_%=:\n\t}"
        :: "r"(m), "r"(par) : "memory");
}
__device__ __forceinline__ void tmem_alloc(uint32_t dst, uint32_t ncols) {
    asm volatile("tcgen05.alloc.cta_group::1.sync.aligned.shared::cta.b32 [%0], %1;"
                 :: "r"(dst), "r"(ncols) : "memory");
}
__device__ __forceinline__ void tmem_dealloc(uint32_t t, uint32_t ncols) {
    asm volatile("tcgen05.relinquish_alloc_permit.cta_group::1.sync.aligned;");
    asm volatile("tcgen05.dealloc.cta_group::1.sync.aligned.b32 %0, %1;" :: "r"(t), "r"(ncols));
}
__device__ __forceinline__ void tc_commit(uint32_t mbar) {
    asm volatile("tcgen05.commit.cta_group::1.mbarrier::arrive::one.shared::cluster.b64 [%0];"
                 :: "r"(mbar) : "memory");
}
__device__ __forceinline__ void mma_f16_ss(uint32_t d, uint64_t ad, uint64_t bd,
                                           uint32_t idesc, bool accum) {
    uint32_t en = accum ? 1u : 0u;
    asm volatile(
        "{\n\t.reg .pred p;\n\tsetp.ne.u32 p, %4, 0;\n\t"
        "tcgen05.mma.cta_group::1.kind::f16 [%0], %1, %2, %3, {%5, %5, %5, %5}, p;\n\t}"
        :: "r"(d), "l"(ad), "l"(bd), "r"(idesc), "r"(en), "r"(0u) : "memory");
}
__device__ __forceinline__ void cp16(uint32_t dst, const void* src) {
    asm volatile("cp.async.cg.shared.global [%0], [%1], 16;" :: "r"(dst), "l"(src));
}
#define CP_COMMIT() asm volatile("cp.async.commit_group;" ::: "memory")
#define CP_WAIT1()  asm volatile("cp.async.wait_group 1;" ::: "memory")
#define CP_WAIT0()  asm volatile("cp.async.wait_group 0;" ::: "memory")
#define TC_FENCE_AFTER()  asm volatile("tcgen05.fence::after_thread_sync;" ::: "memory")
#define TC_FENCE_BEFORE() asm volatile("tcgen05.fence::before_thread_sync;" ::: "memory")
#define PROXY_FENCE()     asm volatile("fence.proxy.async.shared::cta;" ::: "memory")
#define TC_WAIT_LD()      asm volatile("tcgen05.wait::ld.sync.aligned;" ::: "memory")

#define TC_LD_X32(r, addr) \
    asm volatile("tcgen05.ld.sync.aligned.32x32b.x32.b32 " \
        "{%0,%1,%2,%3,%4,%5,%6,%7,%8,%9,%10,%11,%12,%13,%14,%15," \
        "%16,%17,%18,%19,%20,%21,%22,%23,%24,%25,%26,%27,%28,%29,%30,%31}, [%32];" \
        : "=r"((r)[0]),"=r"((r)[1]),"=r"((r)[2]),"=r"((r)[3]), \
          "=r"((r)[4]),"=r"((r)[5]),"=r"((r)[6]),"=r"((r)[7]), \
          "=r"((r)[8]),"=r"((r)[9]),"=r"((r)[10]),"=r"((r)[11]), \
          "=r"((r)[12]),"=r"((r)[13]),"=r"((r)[14]),"=r"((r)[15]), \
          "=r"((r)[16]),"=r"((r)[17]),"=r"((r)[18]),"=r"((r)[19]), \
          "=r"((r)[20]),"=r"((r)[21]),"=r"((r)[22]),"=r"((r)[23]), \
          "=r"((r)[24]),"=r"((r)[25]),"=r"((r)[26]),"=r"((r)[27]), \
          "=r"((r)[28]),"=r"((r)[29]),"=r"((r)[30]),"=r"((r)[31]) \
        : "r"(addr))
#endif

static constexpr uint64_t DESC_BASE_SW128 =
    (uint64_t(2) << 61) | (uint64_t(1) << 46) | (uint64_t(64) << 32) | (uint64_t(1) << 16);
__device__ __forceinline__ uint64_t mk_desc(uint32_t addr) {
    return DESC_BASE_SW128 | ((uint64_t)(addr >> 4) & 0x3FFF);
}

// ============================================================
// main GEMM: CTA tile 128m x 256n, K-stage 64, pure cp.async producers.
// C[m][n] = sum_k A[m][k]*B[n][k], A/B pre-split bf16 hi/lo.
// EPI 0: fp32 store to Cf (ldc)
// EPI 1: bf16 hi/lo split store to Coh/Col (ldc)
// EPI 2: exp(x-60) -> E/ET bf16 hi/lo + row/col partial sums
// ============================================================
#define OFF_MBAR 0
#define OFF_TMEM 32
#define STG_B (96 * 1024)
#define OFF_BUF(s) (1024 + (s) * STG_B)
#define SMEM_NEED (1024 + 2 * STG_B + 1024)
#define TLD 257

static constexpr uint32_t IDESC =
    (1u << 4) | (1u << 7) | (1u << 10) | ((256 / 8) << 17) | ((128 / 16) << 24);

// common EPI-2 tile epilogue: tile holds fp32 S values [128][TLD]
__device__ __forceinline__ void epi_exp(float* tile, int b, int m0, int n0,
                                        int bx, int by, int tid) {
    // phase a: exp + E store + row sums (thread t: row r=t>>1, half h=t&1)
    {
        const int r = tid >> 1, h = tid & 1;
        float* trow = tile + r * TLD + h * 128;
        float rsum = 0.f;
#pragma unroll
        for (int g = 0; g < 16; g++) {
            float e[8];
#pragma unroll
            for (int i = 0; i < 8; i++) {
                e[i] = __expf(trow[g * 8 + i] - 60.f);
                rsum += e[i];
                trow[g * 8 + i] = e[i];
            }
            uint4 H, L; split8(e, H, L);
            const long off = ((long)b * AA + m0 + r) * AA + n0 + h * 128 + g * 8;
            *(uint4*)(g_Eh + off) = H;
            *(uint4*)(g_El + off) = L;
        }
        rsum += __shfl_xor_sync(0xffffffffu, rsum, 1);
        if (h == 0) g_rp[((long)b * 16 + bx) * AA + m0 + r] = rsum;
    }
    __syncthreads();
    // phase b: ET store + col sums (thread t: column n=t)
    {
        const int n = tid;
        float csum = 0.f;
#pragma unroll
        for (int g = 0; g < 16; g++) {
            float e[8];
#pragma unroll
            for (int i = 0; i < 8; i++) {
                e[i] = tile[(g * 8 + i) * TLD + n];
                csum += e[i];
            }
            uint4 H, L; split8(e, H, L);
            const long off = ((long)b * AA + n0 + n) * AA + m0 + g * 8;
            *(uint4*)(g_ETh + off) = H;
            *(uint4*)(g_ETl + off) = L;
        }
        g_cp[((long)b * 32 + by) * AA + n0 + n] = csum;
    }
}

template<int EPI>
__global__ void __launch_bounds__(256) k_gemm(
    const bf16* __restrict__ Agh, const bf16* __restrict__ Agl, long sA, int lda,
    const bf16* __restrict__ Bgh, const bf16* __restrict__ Bgl, long sB, int ldb,
    float* __restrict__ Cf, bf16* __restrict__ Coh, bf16* __restrict__ Col,
    long sC, int ldc, int K)
{
    extern __shared__ char smraw[];
    char* sm = (char*)(((uintptr_t)smraw + 1023) & ~(uintptr_t)1023);
    float* tile = (float*)(sm + 1024);    // reuses pipeline buffers post-mainloop
    const int tid = threadIdx.x, wid = tid >> 5, lid = tid & 31;
    const int b = blockIdx.z;
    const int m0 = blockIdx.y * 128, n0 = blockIdx.x * 256;
    const bf16* Ah = Agh + (long)b * sA + (long)m0 * lda;
    const bf16* Al = Agl + (long)b * sA + (long)m0 * lda;
    const bf16* Bh = Bgh + (long)b * sB + (long)n0 * ldb;
    const bf16* Bl = Bgl + (long)b * sB + (long)n0 * ldb;

#if HAS_TC
    const uint32_t sb = smem_u32(sm);
    if (tid == 0) { mbar_init(sb + OFF_MBAR, 1); mbar_init(sb + OFF_MBAR + 8, 1); }
    if (wid == 0) tmem_alloc(sb + OFF_TMEM, 256);
    __syncthreads();
    uint32_t tmem;
    asm volatile("ld.shared.b32 %0, [%1];" : "=r"(tmem) : "r"(sb + OFF_TMEM));

    const int nst = K / 64;
    auto issue = [&](int s) {
        const uint32_t bufb = sb + OFF_BUF(s & 1);
        const int k0 = s * 64;
#pragma unroll
        for (int i = 0; i < 4; i++) {           // A: 128 rows x 8 chunks
            int idx = tid + i * 256;
            int r = idx >> 3, ch = idx & 7;
            uint32_t d = bufb + (uint32_t)sw128(r * 128 + ch * 16);
            const long so = (long)r * lda + k0 + ch * 8;
            cp16(d, Ah + so);
            cp16(d + 16 * 1024, Al + so);
        }
#pragma unroll
        for (int i = 0; i < 8; i++) {           // B: 256 rows x 8 chunks
            int idx = tid + i * 256;
            int r = idx >> 3, ch = idx & 7;
            uint32_t d = bufb + 32 * 1024 + (uint32_t)sw128(r * 128 + ch * 16);
            const long so = (long)r * ldb + k0 + ch * 8;
            cp16(d, Bh + so);
            cp16(d + 32 * 1024, Bl + so);
        }
        CP_COMMIT();
    };

    issue(0);
    issue(1);
    int ph0 = 0, ph1 = 0;
    for (int s = 0; s < nst; s++) {
        const int buf = s & 1;
        if (s + 1 < nst) CP_WAIT1(); else CP_WAIT0();
        PROXY_FENCE();
        __syncthreads();
        if (wid == 0 && elect_one()) {
            const uint32_t bufb = sb + OFF_BUF(buf);
            uint64_t adh = mk_desc(bufb);
            uint64_t adl = mk_desc(bufb + 16 * 1024);
            uint64_t bdh = mk_desc(bufb + 32 * 1024);
            uint64_t bdl = mk_desc(bufb + 64 * 1024);
#pragma unroll
            for (int k = 0; k < 4; k++) {
                mma_f16_ss(tmem, adh + k * 2, bdh + k * 2, IDESC, !(s == 0 && k == 0));
                mma_f16_ss(tmem, adh + k * 2, bdl + k * 2, IDESC, true);
                mma_f16_ss(tmem, adl + k * 2, bdh + k * 2, IDESC, true);
            }
            tc_commit(sb + OFF_MBAR + buf * 8);
        }
        if (s + 2 < nst) {
            if (buf == 0) { mbar_wait(sb + OFF_MBAR, ph0); ph0 ^= 1; }
            else          { mbar_wait(sb + OFF_MBAR + 8, ph1); ph1 ^= 1; }
            issue(s + 2);
        }
    }
    mbar_wait(sb + OFF_MBAR, ph0);
    mbar_wait(sb + OFF_MBAR + 8, ph1);
    TC_FENCE_AFTER();

    // ---- epilogue: 8 warps, warp w: rows=(w&3)*32+lid, col half=(w>>2)*128 ----
    {
        const int row = (wid & 3) * 32 + lid;
        const int half = wid >> 2;
#pragma unroll
        for (int ch = 0; ch < 4; ch++) {
            uint32_t r[32];
            TC_LD_X32(r, tmem + half * 128 + ch * 32);
            TC_WAIT_LD();
            if (EPI == 0) {
                float* dst = Cf + (long)b * sC + (long)(m0 + row) * ldc
                             + n0 + half * 128 + ch * 32;
#pragma unroll
                for (int j = 0; j < 32; j += 4) {
                    float4 o = make_float4(__uint_as_float(r[j]),   __uint_as_float(r[j+1]),
                                           __uint_as_float(r[j+2]), __uint_as_float(r[j+3]));
                    *(float4*)(dst + j) = o;
                }
            } else if (EPI == 1) {
                const long off = (long)b * sC + (long)(m0 + row) * ldc
                                 + n0 + half * 128 + ch * 32;
#pragma unroll
                for (int g = 0; g < 4; g++) {
                    float e[8];
#pragma unroll
                    for (int i = 0; i < 8; i++) e[i] = __uint_as_float(r[g * 8 + i]);
                    uint4 H, L; split8(e, H, L);
                    *(uint4*)(Coh + off + g * 8) = H;
                    *(uint4*)(Col + off + g * 8) = L;
                }
            } else {
                float* trow = tile + row * TLD + half * 128 + ch * 32;
#pragma unroll
                for (int j = 0; j < 32; j++) trow[j] = __uint_as_float(r[j]);
            }
        }
        TC_FENCE_BEFORE();
    }
    __syncthreads();
    if (wid == 0) tmem_dealloc(tmem, 256);
    if (EPI == 2) {
        __syncthreads();
        epi_exp(tile, b, m0, n0, blockIdx.x, blockIdx.y, tid);
    }

#else  // ---------- wmma fallback (insurance only) ----------
    float* scratch = tile + 128 * TLD;   // 8 warps x 256 floats
    const int wm = wid >> 1, wn = wid & 1;
    for (int nc = 0; nc < 2; nc++) {
        wmma::fragment<wmma::accumulator, 16, 16, 16, float> acc[2][4];
#pragma unroll
        for (int i = 0; i < 2; i++)
#pragma unroll
            for (int j = 0; j < 4; j++) wmma::fill_fragment(acc[i][j], 0.f);
        for (int k0 = 0; k0 < K; k0 += 16) {
            wmma::fragment<wmma::matrix_a, 16, 16, 16, bf16, wmma::row_major> ah, al;
            wmma::fragment<wmma::matrix_b, 16, 16, 16, bf16, wmma::col_major> bh, bl;
#pragma unroll
            for (int i = 0; i < 2; i++) {
                long offA = (long)(wm * 32 + i * 16) * lda + k0;
                wmma::load_matrix_sync(ah, Ah + offA, lda);
                wmma::load_matrix_sync(al, Al + offA, lda);
#pragma unroll
                for (int j = 0; j < 4; j++) {
                    long offB = (long)(nc * 128 + wn * 64 + j * 16) * ldb + k0;
                    wmma::load_matrix_sync(bh, Bh + offB, ldb);
                    wmma::load_matrix_sync(bl, Bl + offB, ldb);
                    wmma::mma_sync(acc[i][j], ah, bh, acc[i][j]);
                    wmma::mma_sync(acc[i][j], ah, bl, acc[i][j]);
                    wmma::mma_sync(acc[i][j], al, bh, acc[i][j]);
                }
            }
        }
        if (EPI == 0) {
#pragma unroll
            for (int i = 0; i < 2; i++)
#pragma unroll
                for (int j = 0; j < 4; j++)
                    wmma::store_matrix_sync(Cf + (long)b * sC
                                            + (long)(m0 + wm * 32 + i * 16) * ldc
                                            + n0 + nc * 128 + wn * 64 + j * 16,
                                            acc[i][j], ldc, wmma::mem_row_major);
        } else {
            // stage via per-warp scratch into tile
#pragma unroll
            for (int i = 0; i < 2; i++)
#pragma unroll
                for (int j = 0; j < 4; j++) {
                    wmma::store_matrix_sync(scratch + wid * 256, acc[i][j], 16,
                                            wmma::mem_row_major);
                    __syncwarp();
#pragma unroll
                    for (int e = 0; e < 8; e++) {
                        int idx = lid + e * 32;
                        int rr = idx >> 4, cc = idx & 15;
                        tile[(wm * 32 + i * 16 + rr) * TLD
                             + nc * 128 + wn * 64 + j * 16 + cc] =
                            scratch[wid * 256 + rr * 16 + cc];
                    }
                    __syncwarp();
                }
        }
    }
    if (EPI == 1) {
        __syncthreads();
        const int r = tid >> 1, h = tid & 1;
        const long off0 = (long)b * sC + (long)(m0 + r) * ldc + n0 + h * 128;
#pragma unroll
        for (int g = 0; g < 16; g++) {
            float e[8];
#pragma unroll
            for (int i = 0; i < 8; i++) e[i] = tile[r * TLD + h * 128 + g * 8 + i];
            uint4 H, L; split8(e, H, L);
            *(uint4*)(Coh + off0 + g * 8) = H;
            *(uint4*)(Col + off0 + g * 8) = L;
        }
    } else if (EPI == 2) {
        __syncthreads();
        epi_exp(tile, b, m0, n0, blockIdx.x, blockIdx.y, tid);
    }
#endif
}

// ---- combine partial sums -> inverse sums ----
__global__ void __launch_bounds__(256) k_combine() {
    const int idx = blockIdx.x * 256 + threadIdx.x;
    const int b = idx / AA, x = idx % AA;
    float rs = 0.f, cs = 0.f;
#pragma unroll
    for (int j = 0; j < 16; j++) rs += g_rp[((long)b * 16 + j) * AA + x];
#pragma unroll
    for (int j = 0; j < 32; j++) cs += g_cp[((long)b * 32 + j) * AA + x];
    g_irs[idx] = 1.f / rs;
    g_ics[idx] = 1.f / cs;
}

// ---- elementwise fp32 -> bf16 hi/lo split ----
__global__ void __launch_bounds__(256) k_split(const float* __restrict__ in,
                                               bf16* __restrict__ oh,
                                               bf16* __restrict__ ol) {
    const long i8 = (long)blockIdx.x * 256 + threadIdx.x;
    float v[8];
    *(float4*)(v)     = __ldg((const float4*)in + i8 * 2);
    *(float4*)(v + 4) = __ldg((const float4*)in + i8 * 2 + 1);
    uint4 H, L; split8(v, H, L);
    *(uint4*)(oh + i8 * 8) = H;
    *(uint4*)(ol + i8 * 8) = L;
}

// ---- generic transpose + split: src[b][r][c] ([R][Cc]) -> out[b][c][r] ----
__global__ void __launch_bounds__(256) k_tsplit(const float* __restrict__ src,
                                                bf16* __restrict__ oh,
                                                bf16* __restrict__ ol,
                                                int R, int Cc, long sbatch) {
    __shared__ float t[32][33];
    const long b = blockIdx.z;
    const int c0 = blockIdx.x * 32, r0 = blockIdx.y * 32;
    const float* s = src + b * sbatch;
    bf16* doh = oh + b * sbatch;
    bf16* dol = ol + b * sbatch;
    const int x = threadIdx.x & 31, y = threadIdx.x >> 5;
#pragma unroll
    for (int i = 0; i < 32; i += 8)
        t[y + i][x] = s[(long)(r0 + y + i) * Cc + c0 + x];
    __syncthreads();
#pragma unroll
    for (int p = 0; p < 2; p++) {
        int idx = threadIdx.x + p * 256;
        int orow = idx >> 4, cp = idx & 15;
        float v0 = t[cp * 2][orow], v1 = t[cp * 2 + 1][orow];
        uint32_t hp = cvt2(v0, v1);
        float q0 = v0 - __uint_as_float(hp << 16);
        float q1 = v1 - __uint_as_float(hp & 0xFFFF0000u);
        uint32_t lp = cvt2(q0, q1);
        long o = (long)(c0 + orow) * R + r0 + cp * 2;
        *(uint32_t*)(doh + o) = hp;
        *(uint32_t*)(dol + o) = lp;
    }
}

// ---- gate + normalize + in-place scale + concat-copy ----
__global__ void __launch_bounds__(256) k_gate(const float* __restrict__ Wg,
                                              const float* __restrict__ Va,
                                              const float* __restrict__ Vb,
                                              float* __restrict__ out) {
    const int side = blockIdx.z, b = blockIdx.y;
    const int n = blockIdx.x * 256 + threadIdx.x;
    const float* orig = (side ? Vb : Va) + (long)b * CC * AA + n;
    const float isn = (side ? g_irs : g_ics)[b * AA + n];
    float* att = out + ((long)(side * BB + b)) * (2L * CC * AA) + n;
    float dot = 0.f;
#pragma unroll 4
    for (int c = 0; c < CC; c++) dot = fmaf(att[(long)c * AA] * isn, Wg[c], dot);
    float mask = isn / (1.f + __expf(-dot));
#pragma unroll 4
    for (int c = 0; c < CC; c++) {
        att[(long)c * AA] *= mask;
        att[(long)(c + CC) * AA] = orig[(long)c * AA];
    }
}

__global__ void k_tail(float* __restrict__ out, long start, long total,
                       const int* __restrict__ isz) {
    long i = start + blockIdx.x * 256L + threadIdx.x;
    if (i < total) out[i] = (float)(*isz);
}

extern "C" void kernel_launch(void* const* d_in, const int* in_sizes, int n_in,
                              void* d_out, int out_size) {
    const float* Va = (const float*)d_in[0];
    const float* Vb = (const float*)d_in[1];
    const float* Wl = (const float*)d_in[2];
    const float* Wg = (const float*)d_in[3];
    const int* isz = (const int*)d_in[4];
    float* out = (float*)d_out;

    bf16 *VaH, *VaL, *VbH, *VbL, *VaTh, *VaTl, *VbTh, *VbTl;
    bf16 *VbWTh, *VbWTl, *WTh, *WTl, *Eh, *El, *ETh, *ETl;
    cudaGetSymbolAddress((void**)&VaH, g_VaH);   cudaGetSymbolAddress((void**)&VaL, g_VaL);
    cudaGetSymbolAddress((void**)&VbH, g_VbH);   cudaGetSymbolAddress((void**)&VbL, g_VbL);
    cudaGetSymbolAddress((void**)&VaTh, g_VaTh); cudaGetSymbolAddress((void**)&VaTl, g_VaTl);
    cudaGetSymbolAddress((void**)&VbTh, g_VbTh); cudaGetSymbolAddress((void**)&VbTl, g_VbTl);
    cudaGetSymbolAddress((void**)&VbWTh, g_VbWTh); cudaGetSymbolAddress((void**)&VbWTl, g_VbWTl);
    cudaGetSymbolAddress((void**)&WTh, g_WTh);   cudaGetSymbolAddress((void**)&WTl, g_WTl);
    cudaGetSymbolAddress((void**)&Eh, g_Eh);     cudaGetSymbolAddress((void**)&El, g_El);
    cudaGetSymbolAddress((void**)&ETh, g_ETh);   cudaGetSymbolAddress((void**)&ETl, g_ETl);

    cudaFuncSetAttribute(k_gemm<0>, cudaFuncAttributeMaxDynamicSharedMemorySize, SMEM_NEED);
    cudaFuncSetAttribute(k_gemm<1>, cudaFuncAttributeMaxDynamicSharedMemorySize, SMEM_NEED);
    cudaFuncSetAttribute(k_gemm<2>, cudaFuncAttributeMaxDynamicSharedMemorySize, SMEM_NEED);

    const long NCA = (long)BB * CC * AA;

    // 1) pre-split + transposes
    k_split<<<(unsigned)(NCA / 2048), 256>>>(Va, VaH, VaL);
    k_split<<<(unsigned)(NCA / 2048), 256>>>(Vb, VbH, VbL);
    k_tsplit<<<dim3(AA / 32, CC / 32, BB), 256>>>(Va, VaTh, VaTl, CC, AA, (long)CC * AA);
    k_tsplit<<<dim3(AA / 32, CC / 32, BB), 256>>>(Vb, VbTh, VbTl, CC, AA, (long)CC * AA);
    k_tsplit<<<dim3(CC / 32, CC / 32, 1), 256>>>(Wl, WTh, WTl, CC, CC, 0);
    // 2) VbWT[n][c] = sum_d VbT[n][d] * WT[c][d]   (tcgen05, split-out)
    k_gemm<1><<<dim3(1, AA / 128, BB), 256, SMEM_NEED>>>(
        VbTh, VbTl, (long)AA * CC, CC,
        WTh, WTl, 0, CC,
        nullptr, VbWTh, VbWTl, (long)AA * CC, CC, CC);
    // 3) S GEMM fused: S[a][n] = sum_c VaT[a][c]*VbWT[n][c]; epilogue -> E/ET + sums
    k_gemm<2><<<dim3(AA / 256, AA / 128, BB), 256, SMEM_NEED>>>(
        VaTh, VaTl, (long)AA * CC, CC,
        VbWTh, VbWTl, (long)AA * CC, CC,
        nullptr, nullptr, nullptr, 0, 0, CC);
    k_combine<<<BB * AA / 256, 256>>>();
    // 4) Va_att_unscaled[c][n] = sum_a Vb[c][a] * ET[n][a]   -> out[0:B]
    k_gemm<0><<<dim3(AA / 256, CC / 128, BB), 256, SMEM_NEED>>>(
        VbH, VbL, (long)CC * AA, AA,
        ETh, ETl, (long)AA * AA, AA,
        out, nullptr, nullptr, 2L * CC * AA, AA, AA);
    // 5) Vb_att_unscaled[c][n] = sum_a Va[c][a] * E[n][a]    -> out[B:2B]
    k_gemm<0><<<dim3(AA / 256, CC / 128, BB), 256, SMEM_NEED>>>(
        VaH, VaL, (long)CC * AA, AA,
        Eh, El, (long)AA * AA, AA,
        out + (long)BB * 2 * CC * AA, nullptr, nullptr, 2L * CC * AA, AA, AA);
    // 6) gate: normalize + mask + concat
    k_gate<<<dim3(AA / 256, BB, 2), 256>>>(Wg, Va, Vb, out);
    // 7) optional tail
    long main_elems = 2L * BB * 2 * CC * AA;
    if ((long)out_size > main_elems) {
        long rem = (long)out_size - main_elems;
        k_tail<<<(unsigned)((rem + 255) / 256), 256>>>(out, main_elems, out_size, isz);
    }
}

// round 17
// speedup vs baseline: 1.0224x; 1.0105x over previous
#include <cuda_runtime.h>
#include <cuda_bf16.h>
#include <mma.h>
#include <math_constants.h>
#include <cstdint>

using namespace nvcuda;
typedef __nv_bfloat16 bf16;

#define BB 4
#define CC 256
#define AA 4096

#if defined(__CUDA_ARCH_FEAT_SM103_ALL) || defined(__CUDA_ARCH_FEAT_SM100_ALL) || \
    defined(__CUDA_ARCH_FEAT_SM101_ALL) || defined(__CUDA_ARCH_FEAT_SM110_ALL)
#define HAS_TC 1
#else
#define HAS_TC 0
#endif

// ---- device scratch ----
__device__ __align__(1024) bf16  g_Eh [(long)BB * AA * AA];    // exp(S-60) hi
__device__ __align__(1024) bf16  g_El [(long)BB * AA * AA];
__device__ __align__(1024) bf16  g_ETh[(long)BB * AA * AA];    // transposed
__device__ __align__(1024) bf16  g_ETl[(long)BB * AA * AA];
__device__ __align__(1024) bf16  g_VaH[(long)BB * CC * AA], g_VaL[(long)BB * CC * AA];
__device__ __align__(1024) bf16  g_VbH[(long)BB * CC * AA], g_VbL[(long)BB * CC * AA];
__device__ __align__(1024) bf16  g_VaTh[(long)BB * AA * CC], g_VaTl[(long)BB * AA * CC];
__device__ __align__(1024) bf16  g_VbTh[(long)BB * AA * CC], g_VbTl[(long)BB * AA * CC];
__device__ __align__(1024) bf16  g_VbWTh[(long)BB * AA * CC], g_VbWTl[(long)BB * AA * CC];
__device__ __align__(1024) bf16  g_WTh[CC * CC], g_WTl[CC * CC];
__device__ float g_rp[(long)BB * 16 * AA], g_cp[(long)BB * 32 * AA];
__device__ float g_irs[BB * AA], g_ics[BB * AA];

// ============================================================
// helpers
// ============================================================
__device__ __forceinline__ uint32_t smem_u32(const void* p) {
    uint32_t a;
    asm("{ .reg .u64 t; cvta.to.shared.u64 t, %1; cvt.u32.u64 %0, t; }" : "=r"(a) : "l"(p));
    return a;
}
__device__ __forceinline__ uint32_t cvt2(float lo, float hi) {
    uint32_t r;
    asm("cvt.rn.bf16x2.f32 %0, %1, %2;" : "=r"(r) : "f"(hi), "f"(lo));
    return r;
}
__device__ __forceinline__ void split8(const float* v, uint4& H, uint4& L) {
    uint32_t h[4], l[4];
#pragma unroll
    for (int i = 0; i < 4; i++) {
        float a = v[2 * i], b = v[2 * i + 1];
        h[i] = cvt2(a, b);
        float ar = a - __uint_as_float(h[i] << 16);
        float br = b - __uint_as_float(h[i] & 0xFFFF0000u);
        l[i] = cvt2(ar, br);
    }
    H = make_uint4(h[0], h[1], h[2], h[3]);
    L = make_uint4(l[0], l[1], l[2], l[3]);
}
__device__ __forceinline__ int sw128(int off) { return off ^ ((off >> 3) & 0x70); }

#if HAS_TC
__device__ __forceinline__ uint32_t elect_one() {
    uint32_t p;
    asm volatile("{ .reg .pred p; elect.sync _|p, 0xFFFFFFFF; selp.b32 %0, 1, 0, p; }" : "=r"(p));
    return p;
}
__device__ __forceinline__ void mbar_init(uint32_t m, uint32_t cnt) {
    asm volatile("mbarrier.init.shared.b64 [%0], %1;" :: "r"(m), "r"(cnt) : "memory");
}
__device__ __forceinline__ void mbar_wait(uint32_t m, uint32_t par) {
    asm volatile(
        "{\n\t.reg .pred P;\n\t"
        "W_%=:\n\t"
        "mbarrier.try_wait.parity.acquire.cta.shared::cta.b64 P, [%0], %1, 0x989680;\n\t"
        "@P bra.uni D_%=;\n\t"
        "bra.uni W_%=;\n\t"
        "D_%=:\n\t}"
        :: "r"(m), "r"(par) : "memory");
}
__device__ __forceinline__ void tmem_alloc(uint32_t dst, uint32_t ncols) {
    asm volatile("tcgen05.alloc.cta_group::1.sync.aligned.shared::cta.b32 [%0], %1;"
                 :: "r"(dst), "r"(ncols) : "memory");
}
__device__ __forceinline__ void tmem_dealloc(uint32_t t, uint32_t ncols) {
    asm volatile("tcgen05.relinquish_alloc_permit.cta_group::1.sync.aligned;");
    asm volatile("tcgen05.dealloc.cta_group::1.sync.aligned.b32 %0, %1;" :: "r"(t), "r"(ncols));
}
__device__ __forceinline__ void tc_commit(uint32_t mbar) {
    asm volatile("tcgen05.commit.cta_group::1.mbarrier::arrive::one.shared::cluster.b64 [%0];"
                 :: "r"(mbar) : "memory");
}
__device__ __forceinline__ void mma_f16_ss(uint32_t d, uint64_t ad, uint64_t bd,
                                           uint32_t idesc, bool accum) {
    uint32_t en = accum ? 1u : 0u;
    asm volatile(
        "{\n\t.reg .pred p;\n\tsetp.ne.u32 p, %4, 0;\n\t"
        "tcgen05.mma.cta_group::1.kind::f16 [%0], %1, %2, %3, {%5, %5, %5, %5}, p;\n\t}"
        :: "r"(d), "l"(ad), "l"(bd), "r"(idesc), "r"(en), "r"(0u) : "memory");
}
__device__ __forceinline__ void cp16(uint32_t dst, const void* src) {
    asm volatile("cp.async.cg.shared.global [%0], [%1], 16;" :: "r"(dst), "l"(src));
}
#define CP_COMMIT() asm volatile("cp.async.commit_group;" ::: "memory")
#define CP_WAIT1()  asm volatile("cp.async.wait_group 1;" ::: "memory")
#define CP_WAIT0()  asm volatile("cp.async.wait_group 0;" ::: "memory")
#define TC_FENCE_AFTER()  asm volatile("tcgen05.fence::after_thread_sync;" ::: "memory")
#define TC_FENCE_BEFORE() asm volatile("tcgen05.fence::before_thread_sync;" ::: "memory")
#define PROXY_FENCE()     asm volatile("fence.proxy.async.shared::cta;" ::: "memory")
#define TC_WAIT_LD()      asm volatile("tcgen05.wait::ld.sync.aligned;" ::: "memory")

#define TC_LD_X32(r, addr) \
    asm volatile("tcgen05.ld.sync.aligned.32x32b.x32.b32 " \
        "{%0,%1,%2,%3,%4,%5,%6,%7,%8,%9,%10,%11,%12,%13,%14,%15," \
        "%16,%17,%18,%19,%20,%21,%22,%23,%24,%25,%26,%27,%28,%29,%30,%31}, [%32];" \
        : "=r"((r)[0]),"=r"((r)[1]),"=r"((r)[2]),"=r"((r)[3]), \
          "=r"((r)[4]),"=r"((r)[5]),"=r"((r)[6]),"=r"((r)[7]), \
          "=r"((r)[8]),"=r"((r)[9]),"=r"((r)[10]),"=r"((r)[11]), \
          "=r"((r)[12]),"=r"((r)[13]),"=r"((r)[14]),"=r"((r)[15]), \
          "=r"((r)[16]),"=r"((r)[17]),"=r"((r)[18]),"=r"((r)[19]), \
          "=r"((r)[20]),"=r"((r)[21]),"=r"((r)[22]),"=r"((r)[23]), \
          "=r"((r)[24]),"=r"((r)[25]),"=r"((r)[26]),"=r"((r)[27]), \
          "=r"((r)[28]),"=r"((r)[29]),"=r"((r)[30]),"=r"((r)[31]) \
        : "r"(addr))
#endif

static constexpr uint64_t DESC_BASE_SW128 =
    (uint64_t(2) << 61) | (uint64_t(1) << 46) | (uint64_t(64) << 32) | (uint64_t(1) << 16);
__device__ __forceinline__ uint64_t mk_desc(uint32_t addr) {
    return DESC_BASE_SW128 | ((uint64_t)(addr >> 4) & 0x3FFF);
}

// ============================================================
// main GEMM: CTA tile 128m x 256n, K-stage 64, pure cp.async producers.
// C[m][n] = sum_k A[m][k]*B[n][k], A/B pre-split bf16 hi/lo.
// EPI 0: fp32 store to Cf (ldc)
// EPI 1: bf16 hi/lo split store to Coh/Col (ldc)
// EPI 2: exp(x-60) -> E/ET bf16 hi/lo + row/col partial sums
// ============================================================
#define OFF_MBAR 0
#define OFF_TMEM 32
#define STG_B (96 * 1024)
#define OFF_BUF(s) (1024 + (s) * STG_B)
#define SMEM_NEED (1024 + 2 * STG_B + 1024)
#define TLD 257

static constexpr uint32_t IDESC =
    (1u << 4) | (1u << 7) | (1u << 10) | ((256 / 8) << 17) | ((128 / 16) << 24);

// common EPI-2 tile epilogue: tile holds fp32 S values [128][TLD]
__device__ __forceinline__ void epi_exp(float* tile, int b, int m0, int n0,
                                        int bx, int by, int tid) {
    // phase a: exp + E store + row sums (thread t: row r=t>>1, half h=t&1)
    {
        const int r = tid >> 1, h = tid & 1;
        float* trow = tile + r * TLD + h * 128;
        float rsum = 0.f;
#pragma unroll
        for (int g = 0; g < 16; g++) {
            float e[8];
#pragma unroll
            for (int i = 0; i < 8; i++) {
                e[i] = __expf(trow[g * 8 + i] - 60.f);
                rsum += e[i];
                trow[g * 8 + i] = e[i];
            }
            uint4 H, L; split8(e, H, L);
            const long off = ((long)b * AA + m0 + r) * AA + n0 + h * 128 + g * 8;
            *(uint4*)(g_Eh + off) = H;
            *(uint4*)(g_El + off) = L;
        }
        rsum += __shfl_xor_sync(0xffffffffu, rsum, 1);
        if (h == 0) g_rp[((long)b * 16 + bx) * AA + m0 + r] = rsum;
    }
    __syncthreads();
    // phase b: ET store + col sums (thread t: column n=t)
    {
        const int n = tid;
        float csum = 0.f;
#pragma unroll
        for (int g = 0; g < 16; g++) {
            float e[8];
#pragma unroll
            for (int i = 0; i < 8; i++) {
                e[i] = tile[(g * 8 + i) * TLD + n];
                csum += e[i];
            }
            uint4 H, L; split8(e, H, L);
            const long off = ((long)b * AA + n0 + n) * AA + m0 + g * 8;
            *(uint4*)(g_ETh + off) = H;
            *(uint4*)(g_ETl + off) = L;
        }
        g_cp[((long)b * 32 + by) * AA + n0 + n] = csum;
    }
}

template<int EPI>
__global__ void __launch_bounds__(256) k_gemm(
    const bf16* __restrict__ Agh, const bf16* __restrict__ Agl, long sA, int lda,
    const bf16* __restrict__ Bgh, const bf16* __restrict__ Bgl, long sB, int ldb,
    float* __restrict__ Cf, bf16* __restrict__ Coh, bf16* __restrict__ Col,
    long sC, int ldc, int K)
{
    extern __shared__ char smraw[];
    char* sm = (char*)(((uintptr_t)smraw + 1023) & ~(uintptr_t)1023);
    float* tile = (float*)(sm + 1024);    // reuses pipeline buffers post-mainloop
    const int tid = threadIdx.x, wid = tid >> 5, lid = tid & 31;
    const int b = blockIdx.z;
    const int m0 = blockIdx.y * 128, n0 = blockIdx.x * 256;
    const bf16* Ah = Agh + (long)b * sA + (long)m0 * lda;
    const bf16* Al = Agl + (long)b * sA + (long)m0 * lda;
    const bf16* Bh = Bgh + (long)b * sB + (long)n0 * ldb;
    const bf16* Bl = Bgl + (long)b * sB + (long)n0 * ldb;

#if HAS_TC
    const uint32_t sb = smem_u32(sm);
    if (tid == 0) { mbar_init(sb + OFF_MBAR, 1); mbar_init(sb + OFF_MBAR + 8, 1); }
    if (wid == 0) tmem_alloc(sb + OFF_TMEM, 256);
    __syncthreads();
    uint32_t tmem;
    asm volatile("ld.shared.b32 %0, [%1];" : "=r"(tmem) : "r"(sb + OFF_TMEM));

    const int nst = K / 64;
    auto issue = [&](int s) {
        const uint32_t bufb = sb + OFF_BUF(s & 1);
        const int k0 = s * 64;
#pragma unroll
        for (int i = 0; i < 4; i++) {           // A: 128 rows x 8 chunks
            int idx = tid + i * 256;
            int r = idx >> 3, ch = idx & 7;
            uint32_t d = bufb + (uint32_t)sw128(r * 128 + ch * 16);
            const long so = (long)r * lda + k0 + ch * 8;
            cp16(d, Ah + so);
            cp16(d + 16 * 1024, Al + so);
        }
#pragma unroll
        for (int i = 0; i < 8; i++) {           // B: 256 rows x 8 chunks
            int idx = tid + i * 256;
            int r = idx >> 3, ch = idx & 7;
            uint32_t d = bufb + 32 * 1024 + (uint32_t)sw128(r * 128 + ch * 16);
            const long so = (long)r * ldb + k0 + ch * 8;
            cp16(d, Bh + so);
            cp16(d + 32 * 1024, Bl + so);
        }
        CP_COMMIT();
    };

    issue(0);
    issue(1);
    int ph0 = 0, ph1 = 0;
    for (int s = 0; s < nst; s++) {
        const int buf = s & 1;
        if (s + 1 < nst) CP_WAIT1(); else CP_WAIT0();
        PROXY_FENCE();
        __syncthreads();
        if (wid == 0 && elect_one()) {
            const uint32_t bufb = sb + OFF_BUF(buf);
            uint64_t adh = mk_desc(bufb);
            uint64_t adl = mk_desc(bufb + 16 * 1024);
            uint64_t bdh = mk_desc(bufb + 32 * 1024);
            uint64_t bdl = mk_desc(bufb + 64 * 1024);
#pragma unroll
            for (int k = 0; k < 4; k++) {
                mma_f16_ss(tmem, adh + k * 2, bdh + k * 2, IDESC, !(s == 0 && k == 0));
                mma_f16_ss(tmem, adh + k * 2, bdl + k * 2, IDESC, true);
                mma_f16_ss(tmem, adl + k * 2, bdh + k * 2, IDESC, true);
            }
            tc_commit(sb + OFF_MBAR + buf * 8);
        }
        if (s + 2 < nst) {
            if (buf == 0) { mbar_wait(sb + OFF_MBAR, ph0); ph0 ^= 1; }
            else          { mbar_wait(sb + OFF_MBAR + 8, ph1); ph1 ^= 1; }
            issue(s + 2);
        }
    }
    mbar_wait(sb + OFF_MBAR, ph0);
    mbar_wait(sb + OFF_MBAR + 8, ph1);
    TC_FENCE_AFTER();

    // ---- epilogue: 8 warps, warp w: rows=(w&3)*32+lid, col half=(w>>2)*128 ----
    {
        const int row = (wid & 3) * 32 + lid;
        const int half = wid >> 2;
#pragma unroll
        for (int ch = 0; ch < 4; ch++) {
            uint32_t r[32];
            TC_LD_X32(r, tmem + half * 128 + ch * 32);
            TC_WAIT_LD();
            if (EPI == 0) {
                float* dst = Cf + (long)b * sC + (long)(m0 + row) * ldc
                             + n0 + half * 128 + ch * 32;
#pragma unroll
                for (int j = 0; j < 32; j += 4) {
                    float4 o = make_float4(__uint_as_float(r[j]),   __uint_as_float(r[j+1]),
                                           __uint_as_float(r[j+2]), __uint_as_float(r[j+3]));
                    *(float4*)(dst + j) = o;
                }
            } else if (EPI == 1) {
                const long off = (long)b * sC + (long)(m0 + row) * ldc
                                 + n0 + half * 128 + ch * 32;
#pragma unroll
                for (int g = 0; g < 4; g++) {
                    float e[8];
#pragma unroll
                    for (int i = 0; i < 8; i++) e[i] = __uint_as_float(r[g * 8 + i]);
                    uint4 H, L; split8(e, H, L);
                    *(uint4*)(Coh + off + g * 8) = H;
                    *(uint4*)(Col + off + g * 8) = L;
                }
            } else {
                float* trow = tile + row * TLD + half * 128 + ch * 32;
#pragma unroll
                for (int j = 0; j < 32; j++) trow[j] = __uint_as_float(r[j]);
            }
        }
        TC_FENCE_BEFORE();
    }
    __syncthreads();
    if (wid == 0) tmem_dealloc(tmem, 256);
    if (EPI == 2) {
        __syncthreads();
        epi_exp(tile, b, m0, n0, blockIdx.x, blockIdx.y, tid);
    }

#else  // ---------- wmma fallback (insurance only) ----------
    float* scratch = tile + 128 * TLD;   // 8 warps x 256 floats
    const int wm = wid >> 1, wn = wid & 1;
    for (int nc = 0; nc < 2; nc++) {
        wmma::fragment<wmma::accumulator, 16, 16, 16, float> acc[2][4];
#pragma unroll
        for (int i = 0; i < 2; i++)
#pragma unroll
            for (int j = 0; j < 4; j++) wmma::fill_fragment(acc[i][j], 0.f);
        for (int k0 = 0; k0 < K; k0 += 16) {
            wmma::fragment<wmma::matrix_a, 16, 16, 16, bf16, wmma::row_major> ah, al;
            wmma::fragment<wmma::matrix_b, 16, 16, 16, bf16, wmma::col_major> bh, bl;
#pragma unroll
            for (int i = 0; i < 2; i++) {
                long offA = (long)(wm * 32 + i * 16) * lda + k0;
                wmma::load_matrix_sync(ah, Ah + offA, lda);
                wmma::load_matrix_sync(al, Al + offA, lda);
#pragma unroll
                for (int j = 0; j < 4; j++) {
                    long offB = (long)(nc * 128 + wn * 64 + j * 16) * ldb + k0;
                    wmma::load_matrix_sync(bh, Bh + offB, ldb);
                    wmma::load_matrix_sync(bl, Bl + offB, ldb);
                    wmma::mma_sync(acc[i][j], ah, bh, acc[i][j]);
                    wmma::mma_sync(acc[i][j], ah, bl, acc[i][j]);
                    wmma::mma_sync(acc[i][j], al, bh, acc[i][j]);
                }
            }
        }
        if (EPI == 0) {
#pragma unroll
            for (int i = 0; i < 2; i++)
#pragma unroll
                for (int j = 0; j < 4; j++)
                    wmma::store_matrix_sync(Cf + (long)b * sC
                                            + (long)(m0 + wm * 32 + i * 16) * ldc
                                            + n0 + nc * 128 + wn * 64 + j * 16,
                                            acc[i][j], ldc, wmma::mem_row_major);
        } else {
            // stage via per-warp scratch into tile
#pragma unroll
            for (int i = 0; i < 2; i++)
#pragma unroll
                for (int j = 0; j < 4; j++) {
                    wmma::store_matrix_sync(scratch + wid * 256, acc[i][j], 16,
                                            wmma::mem_row_major);
                    __syncwarp();
#pragma unroll
                    for (int e = 0; e < 8; e++) {
                        int idx = lid + e * 32;
                        int rr = idx >> 4, cc = idx & 15;
                        tile[(wm * 32 + i * 16 + rr) * TLD
                             + nc * 128 + wn * 64 + j * 16 + cc] =
                            scratch[wid * 256 + rr * 16 + cc];
                    }
                    __syncwarp();
                }
        }
    }
    if (EPI == 1) {
        __syncthreads();
        const int r = tid >> 1, h = tid & 1;
        const long off0 = (long)b * sC + (long)(m0 + r) * ldc + n0 + h * 128;
#pragma unroll
        for (int g = 0; g < 16; g++) {
            float e[8];
#pragma unroll
            for (int i = 0; i < 8; i++) e[i] = tile[r * TLD + h * 128 + g * 8 + i];
            uint4 H, L; split8(e, H, L);
            *(uint4*)(Coh + off0 + g * 8) = H;
            *(uint4*)(Col + off0 + g * 8) = L;
        }
    } else if (EPI == 2) {
        __syncthreads();
        epi_exp(tile, b, m0, n0, blockIdx.x, blockIdx.y, tid);
    }
#endif
}

// ---- combine partial sums -> inverse sums ----
__global__ void __launch_bounds__(256) k_combine() {
    const int idx = blockIdx.x * 256 + threadIdx.x;
    const int b = idx / AA, x = idx % AA;
    float rs = 0.f, cs = 0.f;
#pragma unroll
    for (int j = 0; j < 16; j++) rs += g_rp[((long)b * 16 + j) * AA + x];
#pragma unroll
    for (int j = 0; j < 32; j++) cs += g_cp[((long)b * 32 + j) * AA + x];
    g_irs[idx] = 1.f / rs;
    g_ics[idx] = 1.f / cs;
}

// ---- elementwise fp32 -> bf16 hi/lo split ----
__global__ void __launch_bounds__(256) k_split(const float* __restrict__ in,
                                               bf16* __restrict__ oh,
                                               bf16* __restrict__ ol) {
    const long i8 = (long)blockIdx.x * 256 + threadIdx.x;
    float v[8];
    *(float4*)(v)     = __ldg((const float4*)in + i8 * 2);
    *(float4*)(v + 4) = __ldg((const float4*)in + i8 * 2 + 1);
    uint4 H, L; split8(v, H, L);
    *(uint4*)(oh + i8 * 8) = H;
    *(uint4*)(ol + i8 * 8) = L;
}

// ---- generic transpose + split: src[b][r][c] ([R][Cc]) -> out[b][c][r] ----
__global__ void __launch_bounds__(256) k_tsplit(const float* __restrict__ src,
                                                bf16* __restrict__ oh,
                                                bf16* __restrict__ ol,
                                                int R, int Cc, long sbatch) {
    __shared__ float t[32][33];
    const long b = blockIdx.z;
    const int c0 = blockIdx.x * 32, r0 = blockIdx.y * 32;
    const float* s = src + b * sbatch;
    bf16* doh = oh + b * sbatch;
    bf16* dol = ol + b * sbatch;
    const int x = threadIdx.x & 31, y = threadIdx.x >> 5;
#pragma unroll
    for (int i = 0; i < 32; i += 8)
        t[y + i][x] = s[(long)(r0 + y + i) * Cc + c0 + x];
    __syncthreads();
#pragma unroll
    for (int p = 0; p < 2; p++) {
        int idx = threadIdx.x + p * 256;
        int orow = idx >> 4, cp = idx & 15;
        float v0 = t[cp * 2][orow], v1 = t[cp * 2 + 1][orow];
        uint32_t hp = cvt2(v0, v1);
        float q0 = v0 - __uint_as_float(hp << 16);
        float q1 = v1 - __uint_as_float(hp & 0xFFFF0000u);
        uint32_t lp = cvt2(q0, q1);
        long o = (long)(c0 + orow) * R + r0 + cp * 2;
        *(uint32_t*)(doh + o) = hp;
        *(uint32_t*)(dol + o) = lp;
    }
}

// ---- gate + normalize + in-place scale + concat-copy ----
__global__ void __launch_bounds__(256) k_gate(const float* __restrict__ Wg,
                                              const float* __restrict__ Va,
                                              const float* __restrict__ Vb,
                                              float* __restrict__ out) {
    const int side = blockIdx.z, b = blockIdx.y;
    const int n = blockIdx.x * 256 + threadIdx.x;
    const float* orig = (side ? Vb : Va) + (long)b * CC * AA + n;
    const float isn = (side ? g_irs : g_ics)[b * AA + n];
    float* att = out + ((long)(side * BB + b)) * (2L * CC * AA) + n;
    float dot = 0.f;
#pragma unroll 4
    for (int c = 0; c < CC; c++) dot = fmaf(att[(long)c * AA] * isn, Wg[c], dot);
    float mask = isn / (1.f + __expf(-dot));
#pragma unroll 4
    for (int c = 0; c < CC; c++) {
        att[(long)c * AA] *= mask;
        att[(long)(c + CC) * AA] = orig[(long)c * AA];
    }
}

__global__ void k_tail(float* __restrict__ out, long start, long total,
                       const int* __restrict__ isz) {
    long i = start + blockIdx.x * 256L + threadIdx.x;
    if (i < total) out[i] = (float)(*isz);
}

extern "C" void kernel_launch(void* const* d_in, const int* in_sizes, int n_in,
                              void* d_out, int out_size) {
    const float* Va = (const float*)d_in[0];
    const float* Vb = (const float*)d_in[1];
    const float* Wl = (const float*)d_in[2];
    const float* Wg = (const float*)d_in[3];
    const int* isz = (const int*)d_in[4];
    float* out = (float*)d_out;

    bf16 *VaH, *VaL, *VbH, *VbL, *VaTh, *VaTl, *VbTh, *VbTl;
    bf16 *VbWTh, *VbWTl, *WTh, *WTl, *Eh, *El, *ETh, *ETl;
    cudaGetSymbolAddress((void**)&VaH, g_VaH);   cudaGetSymbolAddress((void**)&VaL, g_VaL);
    cudaGetSymbolAddress((void**)&VbH, g_VbH);   cudaGetSymbolAddress((void**)&VbL, g_VbL);
    cudaGetSymbolAddress((void**)&VaTh, g_VaTh); cudaGetSymbolAddress((void**)&VaTl, g_VaTl);
    cudaGetSymbolAddress((void**)&VbTh, g_VbTh); cudaGetSymbolAddress((void**)&VbTl, g_VbTl);
    cudaGetSymbolAddress((void**)&VbWTh, g_VbWTh); cudaGetSymbolAddress((void**)&VbWTl, g_VbWTl);
    cudaGetSymbolAddress((void**)&WTh, g_WTh);   cudaGetSymbolAddress((void**)&WTl, g_WTl);
    cudaGetSymbolAddress((void**)&Eh, g_Eh);     cudaGetSymbolAddress((void**)&El, g_El);
    cudaGetSymbolAddress((void**)&ETh, g_ETh);   cudaGetSymbolAddress((void**)&ETl, g_ETl);

    cudaFuncSetAttribute(k_gemm<0>, cudaFuncAttributeMaxDynamicSharedMemorySize, SMEM_NEED);
    cudaFuncSetAttribute(k_gemm<1>, cudaFuncAttributeMaxDynamicSharedMemorySize, SMEM_NEED);
    cudaFuncSetAttribute(k_gemm<2>, cudaFuncAttributeMaxDynamicSharedMemorySize, SMEM_NEED);

    const long NCA = (long)BB * CC * AA;

    // 1) pre-split + transposes
    k_split<<<(unsigned)(NCA / 2048), 256>>>(Va, VaH, VaL);
    k_split<<<(unsigned)(NCA / 2048), 256>>>(Vb, VbH, VbL);
    k_tsplit<<<dim3(AA / 32, CC / 32, BB), 256>>>(Va, VaTh, VaTl, CC, AA, (long)CC * AA);
    k_tsplit<<<dim3(AA / 32, CC / 32, BB), 256>>>(Vb, VbTh, VbTl, CC, AA, (long)CC * AA);
    k_tsplit<<<dim3(CC / 32, CC / 32, 1), 256>>>(Wl, WTh, WTl, CC, CC, 0);
    // 2) VbWT[n][c] = sum_d VbT[n][d] * WT[c][d]   (tcgen05, split-out)
    k_gemm<1><<<dim3(1, AA / 128, BB), 256, SMEM_NEED>>>(
        VbTh, VbTl, (long)AA * CC, CC,
        WTh, WTl, 0, CC,
        nullptr, VbWTh, VbWTl, (long)AA * CC, CC, CC);
    // 3) S GEMM fused: S[a][n] = sum_c VaT[a][c]*VbWT[n][c]; epilogue -> E/ET + sums
    k_gemm<2><<<dim3(AA / 256, AA / 128, BB), 256, SMEM_NEED>>>(
        VaTh, VaTl, (long)AA * CC, CC,
        VbWTh, VbWTl, (long)AA * CC, CC,
        nullptr, nullptr, nullptr, 0, 0, CC);
    k_combine<<<BB * AA / 256, 256>>>();
    // 4) Va_att_unscaled[c][n] = sum_a Vb[c][a] * ET[n][a]   -> out[0:B]
    k_gemm<0><<<dim3(AA / 256, CC / 128, BB), 256, SMEM_NEED>>>(
        VbH, VbL, (long)CC * AA, AA,
        ETh, ETl, (long)AA * AA, AA,
        out, nullptr, nullptr, 2L * CC * AA, AA, AA);
    // 5) Vb_att_unscaled[c][n] = sum_a Va[c][a] * E[n][a]    -> out[B:2B]
    k_gemm<0><<<dim3(AA / 256, CC / 128, BB), 256, SMEM_NEED>>>(
        VaH, VaL, (long)CC * AA, AA,
        Eh, El, (long)AA * AA, AA,
        out + (long)BB * 2 * CC * AA, nullptr, nullptr, 2L * CC * AA, AA, AA);
    // 6) gate: normalize + mask + concat
    k_gate<<<dim3(AA / 256, BB, 2), 256>>>(Wg, Va, Vb, out);
    // 7) optional tail
    long main_elems = 2L * BB * 2 * CC * AA;
    if ((long)out_size > main_elems) {
        long rem = (long)out_size - main_elems;
        k_tail<<<(unsigned)((rem + 255) / 256), 256>>>(out, main_elems, out_size, isz);
    }
}